// round 13
// baseline (speedup 1.0000x reference)
#include <cuda_runtime.h>
#include <cuda_bf16.h>
#include <cstdint>

// Problem shape (fixed)
#define N_IMG  16
#define C_IN   3
#define H_IN   224
#define W_IN   224
#define OC     128
#define OH     222
#define OW     222
#define PLANE  (H_IN * W_IN)            // 50176
#define NPIX   (N_IMG * PLANE)          // 802816
#define OPLANE (OH * OW)                // 49284 (even)
#define NPOS   (N_IMG * OPLANE)         // 788544
#define NPAIRS (NPOS / 2)               // 394272 conv threads (2 positions each)

// ---------------- device scratch ------------------------------------------------
// g_scal[0] = amax_x bits, g_scal[1] = amax_w bits, g_scal[2] = amax_v (int)
__device__ unsigned g_scal[3];
__device__ int   g_xq[NPIX];        // packed char4 (c0,c1,c2,0) per pixel
__device__ int4  g_im[NPOS * 2];    // dense im2col: 27 bytes + 5 zero pad (32B/pos)
__device__ int4  g_wqp[OC * 2];     // per oc: 27 wt bytes + pad; word 7 = bias int

static __device__ __forceinline__ int pack4(int a, int b, int c, int d) {
    return (a & 0xFF) | ((b & 0xFF) << 8) | ((c & 0xFF) << 16) | ((d & 0xFF) << 24);
}

// ---------------- K1: abs-max of x (float4 grid) and W --------------------------
__global__ void k_absmax(const float* __restrict__ x, const float* __restrict__ w) {
    int i = blockIdx.x * blockDim.x + threadIdx.x;
    float m = 0.0f;
    if (i < (N_IMG * C_IN * PLANE) / 4) {
        float4 v = reinterpret_cast<const float4*>(x)[i];
        m = fmaxf(fmaxf(fabsf(v.x), fabsf(v.y)), fmaxf(fabsf(v.z), fabsf(v.w)));
    }
    unsigned um = __reduce_max_sync(0xFFFFFFFFu, __float_as_uint(m));
    if ((threadIdx.x & 31) == 0 && um) atomicMax(&g_scal[0], um);

    if (blockIdx.x == 0) {
        float wm = 0.0f;
        for (int j = threadIdx.x; j < OC * C_IN * 9; j += blockDim.x)
            wm = fmaxf(wm, fabsf(w[j]));
        unsigned uw = __reduce_max_sync(0xFFFFFFFFu, __float_as_uint(wm));
        if ((threadIdx.x & 31) == 0) atomicMax(&g_scal[1], uw);
    }
}

// ---------------- K2: quantize x (4 pixels/thread) ; W -> dense 32B records -----
// record byte order: i = tap*3 + channel (i in [0,27)); word 7 = bias int
#define QBLOCKS (NPIX / 1024)   // 784, exact
__global__ void k_quant(const float* __restrict__ x, const float* __restrict__ w,
                        const float* __restrict__ b) {
    const float s_in = fmaxf(__fdiv_rn(__uint_as_float(g_scal[0]), 127.0f), 1e-8f);
    if (blockIdx.x < QBLOCKS) {
        int idx = (blockIdx.x * 256 + threadIdx.x) * 4;
        int n  = idx / PLANE;
        int hw = idx - n * PLANE;
        const float* xp = x + (size_t)n * C_IN * PLANE + hw;
        float4 c0 = *reinterpret_cast<const float4*>(xp);
        float4 c1 = *reinterpret_cast<const float4*>(xp + PLANE);
        float4 c2 = *reinterpret_cast<const float4*>(xp + 2 * PLANE);
        const float ri = __fdiv_rn(1.0f, s_in);
        int4 o;
        {
            int q0 = (int)fminf(fmaxf(rintf(c0.x * ri), -128.f), 127.f);
            int q1 = (int)fminf(fmaxf(rintf(c1.x * ri), -128.f), 127.f);
            int q2 = (int)fminf(fmaxf(rintf(c2.x * ri), -128.f), 127.f);
            o.x = pack4(q0, q1, q2, 0);
        }
        {
            int q0 = (int)fminf(fmaxf(rintf(c0.y * ri), -128.f), 127.f);
            int q1 = (int)fminf(fmaxf(rintf(c1.y * ri), -128.f), 127.f);
            int q2 = (int)fminf(fmaxf(rintf(c2.y * ri), -128.f), 127.f);
            o.y = pack4(q0, q1, q2, 0);
        }
        {
            int q0 = (int)fminf(fmaxf(rintf(c0.z * ri), -128.f), 127.f);
            int q1 = (int)fminf(fmaxf(rintf(c1.z * ri), -128.f), 127.f);
            int q2 = (int)fminf(fmaxf(rintf(c2.z * ri), -128.f), 127.f);
            o.z = pack4(q0, q1, q2, 0);
        }
        {
            int q0 = (int)fminf(fmaxf(rintf(c0.w * ri), -128.f), 127.f);
            int q1 = (int)fminf(fmaxf(rintf(c1.w * ri), -128.f), 127.f);
            int q2 = (int)fminf(fmaxf(rintf(c2.w * ri), -128.f), 127.f);
            o.w = pack4(q0, q1, q2, 0);
        }
        *reinterpret_cast<int4*>(g_xq + idx) = o;
    } else if (threadIdx.x < OC) {
        const float s_w = fmaxf(__fdiv_rn(__uint_as_float(g_scal[1]), 7.0f), 1e-8f);
        int oc = threadIdx.x;
        int m[28];
#pragma unroll
        for (int i = 0; i < 27; i++) {
            int t = i / 3, c = i - t * 3;              // tap-major, channel-minor
            float v = rintf(__fdiv_rn(w[oc * 27 + c * 9 + t], s_w));
            v = fminf(fmaxf(v, -7.0f), 7.0f);
            m[i] = (int)v;
        }
        m[27] = 0;
        int wd[8];
#pragma unroll
        for (int j = 0; j < 7; j++)
            wd[j] = pack4(m[4 * j], m[4 * j + 1], m[4 * j + 2], m[4 * j + 3]);
        float s_b = s_in * s_w;
        float bt = rintf(__fdiv_rn(b[oc], s_b));
        bt = fminf(fmaxf(bt, -2.0e9f), 2.0e9f);
        wd[7] = (int)bt;                               // bias int (never multiplied)
        g_wqp[oc * 2]     = make_int4(wd[0], wd[1], wd[2], wd[3]);
        g_wqp[oc * 2 + 1] = make_int4(wd[4], wd[5], wd[6], wd[7]);
    }
}

// pack one 32B im2col record from 9 pixel words
static __device__ __forceinline__ void pack_rec(int t0, int t1, int t2,
                                                int t3, int t4, int t5,
                                                int t6, int t7, int t8,
                                                int4& lo, int4& hi) {
    lo.x = __byte_perm(t0, t1, 0x4210);
    lo.y = __byte_perm(t1, t2, 0x5421);
    lo.z = __byte_perm(t2, t3, 0x6542);
    lo.w = __byte_perm(t4, t5, 0x4210);
    hi.x = __byte_perm(t5, t6, 0x5421);
    hi.y = __byte_perm(t6, t7, 0x6542);
    hi.z = __byte_perm(t8, 0,  0x4210);
    hi.w = 0;
}

// 7-word dp4a dot as TWO independent chains (4 + 3), merged by one IADD
static __device__ __forceinline__ int dot7(const int4& xa, const int4& xb,
                                           const int4& wa, const int4& wb, int init) {
    int s = __dp4a(xa.x, wa.x, init);
    s = __dp4a(xa.y, wa.y, s);
    s = __dp4a(xa.z, wa.z, s);
    s = __dp4a(xa.w, wa.w, s);
    int t = __dp4a(xb.x, wb.x, 0);
    t = __dp4a(xb.y, wb.y, t);
    t = __dp4a(xb.z, wb.z, t);
    return s + t;
}

// ---------------- K3: FUSED im2col + max pass, oc split across gridDim.y --------
// gridDim = (1541, 2): y selects a 64-oc half. Only y==0 writes g_im.
__global__ void __launch_bounds__(256, 7) k_convmax() {
    __shared__ int4 sw[64 * 2];                        // 2KB: this half's weights
    if (threadIdx.x < 128)
        sw[threadIdx.x] = g_wqp[blockIdx.y * 128 + threadIdx.x];
    __syncthreads();

    int pr = blockIdx.x * 256 + threadIdx.x;           // pair index
    if (pr >= NPAIRS) return;
    int n  = pr / (OPLANE / 2);
    int r2 = (pr - n * (OPLANE / 2)) * 2;
    int oh = r2 / OW;
    int ow = r2 - oh * OW;                             // even, <= 220
    const int* xp = g_xq + (n * H_IN + oh) * W_IN + ow;
    int w00 = xp[0],        w01 = xp[1],            w02 = xp[2],            w03 = xp[3];
    int w10 = xp[W_IN],     w11 = xp[W_IN + 1],     w12 = xp[W_IN + 2],     w13 = xp[W_IN + 3];
    int w20 = xp[2 * W_IN], w21 = xp[2 * W_IN + 1], w22 = xp[2 * W_IN + 2], w23 = xp[2 * W_IN + 3];

    int4 x0a, x0b, x1a, x1b;
    pack_rec(w00, w01, w02, w10, w11, w12, w20, w21, w22, x0a, x0b);
    pack_rec(w01, w02, w03, w11, w12, w13, w21, w22, w23, x1a, x1b);
    if (blockIdx.y == 0) {
        int4* op = g_im + (size_t)pr * 4;
        op[0] = x0a; op[1] = x0b; op[2] = x1a; op[3] = x1b;
    }

    int mx = -2147483647, mn = 2147483647;
#pragma unroll 4
    for (int oc = 0; oc < 64; oc++) {
        int4 wa = sw[oc * 2], wb = sw[oc * 2 + 1];
        int bi = wb.w;
        int a0 = dot7(x0a, x0b, wa, wb, bi);
        int a1 = dot7(x1a, x1b, wa, wb, bi);
        mx = __vimax3_s32(mx, a0, a1);                 // 1 issue instead of 2
        mn = __vimin3_s32(mn, a0, a1);
    }
    int am = __vimax3_s32(mx, -mn, 0);                 // |max| and clamp >= 0
    am = (int)__reduce_max_sync(0xFFFFFFFFu, (unsigned)am);
    if ((threadIdx.x & 31) == 0) atomicMax((int*)&g_scal[2], am);
}

// ---------------- K4: store pass, f32x2 epilogue + streaming stores --------------
__global__ void __launch_bounds__(256, 7) k_convstore(float* __restrict__ out) {
    __shared__ int4 sw[OC * 2];
    sw[threadIdx.x] = g_wqp[threadIdx.x];
    __syncthreads();

    int pr = blockIdx.x * 256 + threadIdx.x;
    if (pr >= NPAIRS) return;

    const int4* ip = g_im + (size_t)pr * 4;            // 64B consecutive per thread
    int4 x0a = ip[0], x0b = ip[1];
    int4 x1a = ip[2], x1b = ip[3];

    const float s_in = fmaxf(__fdiv_rn(__uint_as_float(g_scal[0]), 127.0f), 1e-8f);
    const float s_w  = fmaxf(__fdiv_rn(__uint_as_float(g_scal[1]), 7.0f), 1e-8f);
    float s_b   = s_in * s_w;
    float maxy  = s_b * (float)(int)g_scal[2];
    float s_out = fmaxf(__fdiv_rn(maxy, 127.0f), 1e-8f);
    float kf    = __fdiv_rn(s_b, s_out);
    const float MAGIC = 12582912.0f;                   // 1.5 * 2^23

    // packed f32x2 constants
    unsigned long long k2, m2, nm2, s2;
    asm("mov.b64 %0, {%1,%1};" : "=l"(k2)  : "f"(kf));
    asm("mov.b64 %0, {%1,%1};" : "=l"(m2)  : "f"(MAGIC));
    asm("mov.b64 %0, {%1,%1};" : "=l"(nm2) : "f"(-MAGIC));
    asm("mov.b64 %0, {%1,%1};" : "=l"(s2)  : "f"(s_out));

    // linear output base (no table): p0 + n*(OC-1)*OPLANE
    int p0 = pr * 2;
    int n  = p0 / OPLANE;
    float* obase = out + p0 + (size_t)n * (OC - 1) * OPLANE;

#pragma unroll 4
    for (int oc = 0; oc < OC; oc++) {
        int4 wa = sw[oc * 2], wb = sw[oc * 2 + 1];
        int bi = wb.w;
        int a0 = dot7(x0a, x0b, wa, wb, bi);
        int a1 = dot7(x1a, x1b, wa, wb, bi);
        // magic rounding, both lanes at once: q = rint(a*kf) * s_out
        float f0 = (float)a0, f1 = (float)a1;
        unsigned long long p, q;
        asm("mov.b64 %0, {%1,%2};" : "=l"(p) : "f"(f0), "f"(f1));
        asm("fma.rn.f32x2 %0, %1, %2, %3;" : "=l"(q) : "l"(p), "l"(k2), "l"(m2));
        asm("add.rn.f32x2 %0, %1, %2;" : "=l"(q) : "l"(q), "l"(nm2));
        asm("mul.rn.f32x2 %0, %1, %2;" : "=l"(q) : "l"(q), "l"(s2));
        // streaming 8B store (write-once output, evict-first)
        asm volatile("st.global.cs.b64 [%0], %1;"
                     :: "l"(obase + (size_t)oc * OPLANE), "l"(q) : "memory");
    }
}

// ---------------- launcher --------------------------------------------------------
extern "C" void kernel_launch(void* const* d_in, const int* in_sizes, int n_in,
                              void* d_out, int out_size) {
    const float *x = nullptr, *w = nullptr, *b = nullptr;
    for (int i = 0; i < n_in; i++) {
        if (in_sizes[i] == N_IMG * C_IN * PLANE)      x = (const float*)d_in[i];
        else if (in_sizes[i] == OC * C_IN * 9)        w = (const float*)d_in[i];
        else if (in_sizes[i] == OC)                   b = (const float*)d_in[i];
    }
    float* out = (float*)d_out;

    void* scal_addr = nullptr;
    cudaGetSymbolAddress(&scal_addr, g_scal);
    cudaMemsetAsync(scal_addr, 0, 3 * sizeof(unsigned), 0);

    int n4 = (N_IMG * C_IN * PLANE) / 4;
    k_absmax<<<(n4 + 255) / 256, 256>>>(x, w);

    k_quant<<<QBLOCKS + 1, 256>>>(x, w, b);

    int cblocks = (NPAIRS + 255) / 256;   // 1541
    dim3 mg(cblocks, 2);
    k_convmax<<<mg, 256>>>();
    k_convstore<<<cblocks, 256>>>(out);
}

// round 14
// speedup vs baseline: 1.0502x; 1.0502x over previous
#include <cuda_runtime.h>
#include <cuda_bf16.h>
#include <cstdint>

// Problem shape (fixed)
#define N_IMG  16
#define C_IN   3
#define H_IN   224
#define W_IN   224
#define OC     128
#define OH     222
#define OW     222
#define PLANE  (H_IN * W_IN)            // 50176
#define NPIX   (N_IMG * PLANE)          // 802816
#define OPLANE (OH * OW)                // 49284 (even)
#define NPOS   (N_IMG * OPLANE)         // 788544
#define NPAIRS (NPOS / 2)               // 394272 conv threads (2 positions each)
#define OCSPLIT 4                        // convmax oc split
#define OCS     (OC / OCSPLIT)           // 32 ocs per convmax thread

// ---------------- device scratch ------------------------------------------------
// g_scal[0] = amax_x bits, g_scal[1] = amax_w bits, g_scal[2] = amax_v (int)
__device__ unsigned g_scal[3];
__device__ int   g_xq[NPIX];        // packed char4 (c0,c1,c2,0) per pixel
__device__ int4  g_im[NPOS * 2];    // dense im2col: 27 bytes + 5 zero pad (32B/pos)
__device__ int4  g_wqp[OC * 2];     // per oc: 27 wt bytes + pad; word 7 = bias int

static __device__ __forceinline__ int pack4(int a, int b, int c, int d) {
    return (a & 0xFF) | ((b & 0xFF) << 8) | ((c & 0xFF) << 16) | ((d & 0xFF) << 24);
}

// ---------------- K1: abs-max of x (float4 grid) and W --------------------------
__global__ void k_absmax(const float* __restrict__ x, const float* __restrict__ w) {
    int i = blockIdx.x * blockDim.x + threadIdx.x;
    float m = 0.0f;
    if (i < (N_IMG * C_IN * PLANE) / 4) {
        float4 v = reinterpret_cast<const float4*>(x)[i];
        m = fmaxf(fmaxf(fabsf(v.x), fabsf(v.y)), fmaxf(fabsf(v.z), fabsf(v.w)));
    }
    unsigned um = __reduce_max_sync(0xFFFFFFFFu, __float_as_uint(m));
    if ((threadIdx.x & 31) == 0 && um) atomicMax(&g_scal[0], um);

    if (blockIdx.x == 0) {
        float wm = 0.0f;
        for (int j = threadIdx.x; j < OC * C_IN * 9; j += blockDim.x)
            wm = fmaxf(wm, fabsf(w[j]));
        unsigned uw = __reduce_max_sync(0xFFFFFFFFu, __float_as_uint(wm));
        if ((threadIdx.x & 31) == 0) atomicMax(&g_scal[1], uw);
    }
}

// ---------------- K2: quantize x (4 pixels/thread) ; W -> dense 32B records -----
// record byte order: i = tap*3 + channel (i in [0,27)); word 7 = bias int
#define QBLOCKS (NPIX / 1024)   // 784, exact
__global__ void k_quant(const float* __restrict__ x, const float* __restrict__ w,
                        const float* __restrict__ b) {
    const float s_in = fmaxf(__fdiv_rn(__uint_as_float(g_scal[0]), 127.0f), 1e-8f);
    if (blockIdx.x < QBLOCKS) {
        int idx = (blockIdx.x * 256 + threadIdx.x) * 4;
        int n  = idx / PLANE;
        int hw = idx - n * PLANE;
        const float* xp = x + (size_t)n * C_IN * PLANE + hw;
        float4 c0 = *reinterpret_cast<const float4*>(xp);
        float4 c1 = *reinterpret_cast<const float4*>(xp + PLANE);
        float4 c2 = *reinterpret_cast<const float4*>(xp + 2 * PLANE);
        const float ri = __fdiv_rn(1.0f, s_in);
        int4 o;
        {
            int q0 = (int)fminf(fmaxf(rintf(c0.x * ri), -128.f), 127.f);
            int q1 = (int)fminf(fmaxf(rintf(c1.x * ri), -128.f), 127.f);
            int q2 = (int)fminf(fmaxf(rintf(c2.x * ri), -128.f), 127.f);
            o.x = pack4(q0, q1, q2, 0);
        }
        {
            int q0 = (int)fminf(fmaxf(rintf(c0.y * ri), -128.f), 127.f);
            int q1 = (int)fminf(fmaxf(rintf(c1.y * ri), -128.f), 127.f);
            int q2 = (int)fminf(fmaxf(rintf(c2.y * ri), -128.f), 127.f);
            o.y = pack4(q0, q1, q2, 0);
        }
        {
            int q0 = (int)fminf(fmaxf(rintf(c0.z * ri), -128.f), 127.f);
            int q1 = (int)fminf(fmaxf(rintf(c1.z * ri), -128.f), 127.f);
            int q2 = (int)fminf(fmaxf(rintf(c2.z * ri), -128.f), 127.f);
            o.z = pack4(q0, q1, q2, 0);
        }
        {
            int q0 = (int)fminf(fmaxf(rintf(c0.w * ri), -128.f), 127.f);
            int q1 = (int)fminf(fmaxf(rintf(c1.w * ri), -128.f), 127.f);
            int q2 = (int)fminf(fmaxf(rintf(c2.w * ri), -128.f), 127.f);
            o.w = pack4(q0, q1, q2, 0);
        }
        *reinterpret_cast<int4*>(g_xq + idx) = o;
    } else if (threadIdx.x < OC) {
        const float s_w = fmaxf(__fdiv_rn(__uint_as_float(g_scal[1]), 7.0f), 1e-8f);
        int oc = threadIdx.x;
        int m[28];
#pragma unroll
        for (int i = 0; i < 27; i++) {
            int t = i / 3, c = i - t * 3;              // tap-major, channel-minor
            float v = rintf(__fdiv_rn(w[oc * 27 + c * 9 + t], s_w));
            v = fminf(fmaxf(v, -7.0f), 7.0f);
            m[i] = (int)v;
        }
        m[27] = 0;
        int wd[8];
#pragma unroll
        for (int j = 0; j < 7; j++)
            wd[j] = pack4(m[4 * j], m[4 * j + 1], m[4 * j + 2], m[4 * j + 3]);
        float s_b = s_in * s_w;
        float bt = rintf(__fdiv_rn(b[oc], s_b));
        bt = fminf(fmaxf(bt, -2.0e9f), 2.0e9f);
        wd[7] = (int)bt;                               // bias int (never multiplied)
        g_wqp[oc * 2]     = make_int4(wd[0], wd[1], wd[2], wd[3]);
        g_wqp[oc * 2 + 1] = make_int4(wd[4], wd[5], wd[6], wd[7]);
    }
}

// pack one 32B im2col record from 9 pixel words
static __device__ __forceinline__ void pack_rec(int t0, int t1, int t2,
                                                int t3, int t4, int t5,
                                                int t6, int t7, int t8,
                                                int4& lo, int4& hi) {
    lo.x = __byte_perm(t0, t1, 0x4210);
    lo.y = __byte_perm(t1, t2, 0x5421);
    lo.z = __byte_perm(t2, t3, 0x6542);
    lo.w = __byte_perm(t4, t5, 0x4210);
    hi.x = __byte_perm(t5, t6, 0x5421);
    hi.y = __byte_perm(t6, t7, 0x6542);
    hi.z = __byte_perm(t8, 0,  0x4210);
    hi.w = 0;
}

// 7-word dp4a dot as TWO independent chains (4 + 3), merged by one IADD
static __device__ __forceinline__ int dot7(const int4& xa, const int4& xb,
                                           const int4& wa, const int4& wb, int init) {
    int s = __dp4a(xa.x, wa.x, init);
    s = __dp4a(xa.y, wa.y, s);
    s = __dp4a(xa.z, wa.z, s);
    s = __dp4a(xa.w, wa.w, s);
    int t = __dp4a(xb.x, wb.x, 0);
    t = __dp4a(xb.y, wb.y, t);
    t = __dp4a(xb.z, wb.z, t);
    return s + t;
}

// ---------------- K3: FUSED im2col + max pass, oc split across gridDim.y --------
// gridDim = (1541, 4): y selects a 32-oc slice. Only y==0 writes g_im.
__global__ void __launch_bounds__(256, 6) k_convmax() {
    __shared__ int4 sw[OCS * 2];                       // 1KB: this slice's weights
    if (threadIdx.x < OCS * 2)
        sw[threadIdx.x] = g_wqp[blockIdx.y * (OCS * 2) + threadIdx.x];
    __syncthreads();

    int pr = blockIdx.x * 256 + threadIdx.x;           // pair index
    if (pr >= NPAIRS) return;
    int n  = pr / (OPLANE / 2);
    int r2 = (pr - n * (OPLANE / 2)) * 2;
    int oh = r2 / OW;
    int ow = r2 - oh * OW;                             // even, <= 220
    const int* xp = g_xq + (n * H_IN + oh) * W_IN + ow;
    int w00 = xp[0],        w01 = xp[1],            w02 = xp[2],            w03 = xp[3];
    int w10 = xp[W_IN],     w11 = xp[W_IN + 1],     w12 = xp[W_IN + 2],     w13 = xp[W_IN + 3];
    int w20 = xp[2 * W_IN], w21 = xp[2 * W_IN + 1], w22 = xp[2 * W_IN + 2], w23 = xp[2 * W_IN + 3];

    int4 x0a, x0b, x1a, x1b;
    pack_rec(w00, w01, w02, w10, w11, w12, w20, w21, w22, x0a, x0b);
    pack_rec(w01, w02, w03, w11, w12, w13, w21, w22, w23, x1a, x1b);
    if (blockIdx.y == 0) {
        int4* op = g_im + (size_t)pr * 4;
        op[0] = x0a; op[1] = x0b; op[2] = x1a; op[3] = x1b;
    }

    int mx = -2147483647, mn = 2147483647;
#pragma unroll 4
    for (int oc = 0; oc < OCS; oc++) {
        int4 wa = sw[oc * 2], wb = sw[oc * 2 + 1];
        int bi = wb.w;
        int a0 = dot7(x0a, x0b, wa, wb, bi);
        int a1 = dot7(x1a, x1b, wa, wb, bi);
        mx = __vimax3_s32(mx, a0, a1);
        mn = __vimin3_s32(mn, a0, a1);
    }
    int am = __vimax3_s32(mx, -mn, 0);                 // |max| and clamp >= 0
    am = (int)__reduce_max_sync(0xFFFFFFFFu, (unsigned)am);
    if ((threadIdx.x & 31) == 0) atomicMax((int*)&g_scal[2], am);
}

// ---------------- K4: store pass, f32x2 epilogue + streaming stores --------------
__global__ void __launch_bounds__(256, 6) k_convstore(float* __restrict__ out) {
    __shared__ int4 sw[OC * 2];
    sw[threadIdx.x] = g_wqp[threadIdx.x];
    __syncthreads();

    int pr = blockIdx.x * 256 + threadIdx.x;
    if (pr >= NPAIRS) return;

    const int4* ip = g_im + (size_t)pr * 4;            // 64B consecutive per thread
    int4 x0a = ip[0], x0b = ip[1];
    int4 x1a = ip[2], x1b = ip[3];

    const float s_in = fmaxf(__fdiv_rn(__uint_as_float(g_scal[0]), 127.0f), 1e-8f);
    const float s_w  = fmaxf(__fdiv_rn(__uint_as_float(g_scal[1]), 7.0f), 1e-8f);
    float s_b   = s_in * s_w;
    float maxy  = s_b * (float)(int)g_scal[2];
    float s_out = fmaxf(__fdiv_rn(maxy, 127.0f), 1e-8f);
    float kf    = __fdiv_rn(s_b, s_out);
    const float MAGIC = 12582912.0f;                   // 1.5 * 2^23

    // packed f32x2 constants
    unsigned long long k2, m2, nm2, s2;
    asm("mov.b64 %0, {%1,%1};" : "=l"(k2)  : "f"(kf));
    asm("mov.b64 %0, {%1,%1};" : "=l"(m2)  : "f"(MAGIC));
    asm("mov.b64 %0, {%1,%1};" : "=l"(nm2) : "f"(-MAGIC));
    asm("mov.b64 %0, {%1,%1};" : "=l"(s2)  : "f"(s_out));

    // linear output base (no table): p0 + n*(OC-1)*OPLANE
    int p0 = pr * 2;
    int n  = p0 / OPLANE;
    float* obase = out + p0 + (size_t)n * (OC - 1) * OPLANE;

#pragma unroll 4
    for (int oc = 0; oc < OC; oc++) {
        int4 wa = sw[oc * 2], wb = sw[oc * 2 + 1];
        int bi = wb.w;
        int a0 = dot7(x0a, x0b, wa, wb, bi);
        int a1 = dot7(x1a, x1b, wa, wb, bi);
        // magic rounding, both lanes at once: q = rint(a*kf) * s_out
        float f0 = (float)a0, f1 = (float)a1;
        unsigned long long p, q;
        asm("mov.b64 %0, {%1,%2};" : "=l"(p) : "f"(f0), "f"(f1));
        asm("fma.rn.f32x2 %0, %1, %2, %3;" : "=l"(q) : "l"(p), "l"(k2), "l"(m2));
        asm("add.rn.f32x2 %0, %1, %2;" : "=l"(q) : "l"(q), "l"(nm2));
        asm("mul.rn.f32x2 %0, %1, %2;" : "=l"(q) : "l"(q), "l"(s2));
        // streaming 8B store (write-once output, evict-first)
        asm volatile("st.global.cs.b64 [%0], %1;"
                     :: "l"(obase + (size_t)oc * OPLANE), "l"(q) : "memory");
    }
}

// ---------------- launcher --------------------------------------------------------
extern "C" void kernel_launch(void* const* d_in, const int* in_sizes, int n_in,
                              void* d_out, int out_size) {
    const float *x = nullptr, *w = nullptr, *b = nullptr;
    for (int i = 0; i < n_in; i++) {
        if (in_sizes[i] == N_IMG * C_IN * PLANE)      x = (const float*)d_in[i];
        else if (in_sizes[i] == OC * C_IN * 9)        w = (const float*)d_in[i];
        else if (in_sizes[i] == OC)                   b = (const float*)d_in[i];
    }
    float* out = (float*)d_out;

    void* scal_addr = nullptr;
    cudaGetSymbolAddress(&scal_addr, g_scal);
    cudaMemsetAsync(scal_addr, 0, 3 * sizeof(unsigned), 0);

    int n4 = (N_IMG * C_IN * PLANE) / 4;
    k_absmax<<<(n4 + 255) / 256, 256>>>(x, w);

    k_quant<<<QBLOCKS + 1, 256>>>(x, w, b);

    int cblocks = (NPAIRS + 255) / 256;   // 1541
    dim3 mg(cblocks, OCSPLIT);
    k_convmax<<<mg, 256>>>();
    k_convstore<<<cblocks, 256>>>(out);
}

// round 15
// speedup vs baseline: 1.0728x; 1.0215x over previous
#include <cuda_runtime.h>
#include <cuda_bf16.h>
#include <cstdint>

// Problem shape (fixed)
#define N_IMG  16
#define C_IN   3
#define H_IN   224
#define W_IN   224
#define OC     128
#define OH     222
#define OW     222
#define PLANE  (H_IN * W_IN)            // 50176
#define NPIX   (N_IMG * PLANE)          // 802816
#define OPLANE (OH * OW)                // 49284 (even)
#define NPOS   (N_IMG * OPLANE)         // 788544
#define NPAIRS (NPOS / 2)               // 394272 conv threads (2 positions each)

// ---------------- device scratch ------------------------------------------------
// g_scal[0] = amax_x bits, g_scal[1] = amax_w bits, g_scal[2] = amax_v (int)
__device__ unsigned g_scal[3];
__device__ int   g_xq[NPIX];        // packed char4 (c0,c1,c2,0) per pixel
__device__ int4  g_im[NPOS * 2];    // dense im2col: 27 bytes + 5 zero pad (32B/pos)
__device__ int4  g_wqp[OC * 2];     // per oc: 27 wt bytes + pad; word 7 = bias int

static __device__ __forceinline__ int pack4(int a, int b, int c, int d) {
    return (a & 0xFF) | ((b & 0xFF) << 8) | ((c & 0xFF) << 16) | ((d & 0xFF) << 24);
}

// ---------------- K1: abs-max of x (float4 grid) and W --------------------------
__global__ void k_absmax(const float* __restrict__ x, const float* __restrict__ w) {
    int i = blockIdx.x * blockDim.x + threadIdx.x;
    float m = 0.0f;
    if (i < (N_IMG * C_IN * PLANE) / 4) {
        float4 v = reinterpret_cast<const float4*>(x)[i];
        m = fmaxf(fmaxf(fabsf(v.x), fabsf(v.y)), fmaxf(fabsf(v.z), fabsf(v.w)));
    }
    unsigned um = __reduce_max_sync(0xFFFFFFFFu, __float_as_uint(m));
    if ((threadIdx.x & 31) == 0 && um) atomicMax(&g_scal[0], um);

    if (blockIdx.x == 0) {
        float wm = 0.0f;
        for (int j = threadIdx.x; j < OC * C_IN * 9; j += blockDim.x)
            wm = fmaxf(wm, fabsf(w[j]));
        unsigned uw = __reduce_max_sync(0xFFFFFFFFu, __float_as_uint(wm));
        if ((threadIdx.x & 31) == 0) atomicMax(&g_scal[1], uw);
    }
}

// ---------------- K2: quantize x (4 pixels/thread) ; W -> dense 32B records -----
// record byte order: i = tap*3 + channel (i in [0,27)); word 7 = bias int
#define QBLOCKS (NPIX / 1024)   // 784, exact
__global__ void k_quant(const float* __restrict__ x, const float* __restrict__ w,
                        const float* __restrict__ b) {
    const float s_in = fmaxf(__fdiv_rn(__uint_as_float(g_scal[0]), 127.0f), 1e-8f);
    if (blockIdx.x < QBLOCKS) {
        int idx = (blockIdx.x * 256 + threadIdx.x) * 4;
        int n  = idx / PLANE;
        int hw = idx - n * PLANE;
        const float* xp = x + (size_t)n * C_IN * PLANE + hw;
        float4 c0 = *reinterpret_cast<const float4*>(xp);
        float4 c1 = *reinterpret_cast<const float4*>(xp + PLANE);
        float4 c2 = *reinterpret_cast<const float4*>(xp + 2 * PLANE);
        const float ri = __fdiv_rn(1.0f, s_in);
        int4 o;
        {
            int q0 = (int)fminf(fmaxf(rintf(c0.x * ri), -128.f), 127.f);
            int q1 = (int)fminf(fmaxf(rintf(c1.x * ri), -128.f), 127.f);
            int q2 = (int)fminf(fmaxf(rintf(c2.x * ri), -128.f), 127.f);
            o.x = pack4(q0, q1, q2, 0);
        }
        {
            int q0 = (int)fminf(fmaxf(rintf(c0.y * ri), -128.f), 127.f);
            int q1 = (int)fminf(fmaxf(rintf(c1.y * ri), -128.f), 127.f);
            int q2 = (int)fminf(fmaxf(rintf(c2.y * ri), -128.f), 127.f);
            o.y = pack4(q0, q1, q2, 0);
        }
        {
            int q0 = (int)fminf(fmaxf(rintf(c0.z * ri), -128.f), 127.f);
            int q1 = (int)fminf(fmaxf(rintf(c1.z * ri), -128.f), 127.f);
            int q2 = (int)fminf(fmaxf(rintf(c2.z * ri), -128.f), 127.f);
            o.z = pack4(q0, q1, q2, 0);
        }
        {
            int q0 = (int)fminf(fmaxf(rintf(c0.w * ri), -128.f), 127.f);
            int q1 = (int)fminf(fmaxf(rintf(c1.w * ri), -128.f), 127.f);
            int q2 = (int)fminf(fmaxf(rintf(c2.w * ri), -128.f), 127.f);
            o.w = pack4(q0, q1, q2, 0);
        }
        *reinterpret_cast<int4*>(g_xq + idx) = o;
    } else if (threadIdx.x < OC) {
        const float s_w = fmaxf(__fdiv_rn(__uint_as_float(g_scal[1]), 7.0f), 1e-8f);
        int oc = threadIdx.x;
        int m[28];
#pragma unroll
        for (int i = 0; i < 27; i++) {
            int t = i / 3, c = i - t * 3;              // tap-major, channel-minor
            float v = rintf(__fdiv_rn(w[oc * 27 + c * 9 + t], s_w));
            v = fminf(fmaxf(v, -7.0f), 7.0f);
            m[i] = (int)v;
        }
        m[27] = 0;
        int wd[8];
#pragma unroll
        for (int j = 0; j < 7; j++)
            wd[j] = pack4(m[4 * j], m[4 * j + 1], m[4 * j + 2], m[4 * j + 3]);
        float s_b = s_in * s_w;
        float bt = rintf(__fdiv_rn(b[oc], s_b));
        bt = fminf(fmaxf(bt, -2.0e9f), 2.0e9f);
        wd[7] = (int)bt;                               // bias int (never multiplied)
        g_wqp[oc * 2]     = make_int4(wd[0], wd[1], wd[2], wd[3]);
        g_wqp[oc * 2 + 1] = make_int4(wd[4], wd[5], wd[6], wd[7]);
    }
}

// pack one 32B im2col record from 9 pixel words
static __device__ __forceinline__ void pack_rec(int t0, int t1, int t2,
                                                int t3, int t4, int t5,
                                                int t6, int t7, int t8,
                                                int4& lo, int4& hi) {
    lo.x = __byte_perm(t0, t1, 0x4210);
    lo.y = __byte_perm(t1, t2, 0x5421);
    lo.z = __byte_perm(t2, t3, 0x6542);
    lo.w = __byte_perm(t4, t5, 0x4210);
    hi.x = __byte_perm(t5, t6, 0x5421);
    hi.y = __byte_perm(t6, t7, 0x6542);
    hi.z = __byte_perm(t8, 0,  0x4210);
    hi.w = 0;
}

// 7-word dp4a dot as TWO independent chains (4 + 3), merged by one IADD
static __device__ __forceinline__ int dot7(const int4& xa, const int4& xb,
                                           const int4& wa, const int4& wb, int init) {
    int s = __dp4a(xa.x, wa.x, init);
    s = __dp4a(xa.y, wa.y, s);
    s = __dp4a(xa.z, wa.z, s);
    s = __dp4a(xa.w, wa.w, s);
    int t = __dp4a(xb.x, wb.x, 0);
    t = __dp4a(xb.y, wb.y, t);
    t = __dp4a(xb.z, wb.z, t);
    return s + t;
}

// ---------------- K3: FUSED im2col + max pass, oc split across gridDim.y --------
// gridDim = (1541, 2): y selects a 64-oc half. Only y==0 writes g_im.
__global__ void __launch_bounds__(256, 6) k_convmax() {
    __shared__ int4 sw[64 * 2];                        // 2KB: this half's weights
    if (threadIdx.x < 128)
        sw[threadIdx.x] = g_wqp[blockIdx.y * 128 + threadIdx.x];
    __syncthreads();

    int pr = blockIdx.x * 256 + threadIdx.x;           // pair index
    if (pr >= NPAIRS) return;
    int n  = pr / (OPLANE / 2);
    int r2 = (pr - n * (OPLANE / 2)) * 2;
    int oh = r2 / OW;
    int ow = r2 - oh * OW;                             // even, <= 220
    const int* xp = g_xq + (n * H_IN + oh) * W_IN + ow;
    int w00 = xp[0],        w01 = xp[1],            w02 = xp[2],            w03 = xp[3];
    int w10 = xp[W_IN],     w11 = xp[W_IN + 1],     w12 = xp[W_IN + 2],     w13 = xp[W_IN + 3];
    int w20 = xp[2 * W_IN], w21 = xp[2 * W_IN + 1], w22 = xp[2 * W_IN + 2], w23 = xp[2 * W_IN + 3];

    int4 x0a, x0b, x1a, x1b;
    pack_rec(w00, w01, w02, w10, w11, w12, w20, w21, w22, x0a, x0b);
    pack_rec(w01, w02, w03, w11, w12, w13, w21, w22, w23, x1a, x1b);
    if (blockIdx.y == 0) {
        int4* op = g_im + (size_t)pr * 4;
        op[0] = x0a; op[1] = x0b; op[2] = x1a; op[3] = x1b;
    }

    int mx = -2147483647, mn = 2147483647;
#pragma unroll 4
    for (int oc = 0; oc < 64; oc++) {
        int4 wa = sw[oc * 2], wb = sw[oc * 2 + 1];
        int bi = wb.w;
        int a0 = dot7(x0a, x0b, wa, wb, bi);
        int a1 = dot7(x1a, x1b, wa, wb, bi);
        mx = __vimax3_s32(mx, a0, a1);
        mn = __vimin3_s32(mn, a0, a1);
    }
    int am = __vimax3_s32(mx, -mn, 0);                 // |max| and clamp >= 0
    am = (int)__reduce_max_sync(0xFFFFFFFFu, (unsigned)am);
    if ((threadIdx.x & 31) == 0) atomicMax((int*)&g_scal[2], am);
}

// ---------------- K4: store pass, oc split across gridDim.y ----------------------
// gridDim = (1541, 2): y selects a 64-oc half. f32x2 epilogue + streaming stores.
__global__ void __launch_bounds__(256, 6) k_convstore(float* __restrict__ out) {
    __shared__ int4 sw[64 * 2];                        // 2KB: this half's weights
    if (threadIdx.x < 128)
        sw[threadIdx.x] = g_wqp[blockIdx.y * 128 + threadIdx.x];
    __syncthreads();

    int pr = blockIdx.x * 256 + threadIdx.x;
    if (pr >= NPAIRS) return;

    const int4* ip = g_im + (size_t)pr * 4;            // 64B consecutive per thread
    int4 x0a = ip[0], x0b = ip[1];
    int4 x1a = ip[2], x1b = ip[3];

    const float s_in = fmaxf(__fdiv_rn(__uint_as_float(g_scal[0]), 127.0f), 1e-8f);
    const float s_w  = fmaxf(__fdiv_rn(__uint_as_float(g_scal[1]), 7.0f), 1e-8f);
    float s_b   = s_in * s_w;
    float maxy  = s_b * (float)(int)g_scal[2];
    float s_out = fmaxf(__fdiv_rn(maxy, 127.0f), 1e-8f);
    float kf    = __fdiv_rn(s_b, s_out);
    const float MAGIC = 12582912.0f;                   // 1.5 * 2^23

    // packed f32x2 constants
    unsigned long long k2, m2, nm2, s2;
    asm("mov.b64 %0, {%1,%1};" : "=l"(k2)  : "f"(kf));
    asm("mov.b64 %0, {%1,%1};" : "=l"(m2)  : "f"(MAGIC));
    asm("mov.b64 %0, {%1,%1};" : "=l"(nm2) : "f"(-MAGIC));
    asm("mov.b64 %0, {%1,%1};" : "=l"(s2)  : "f"(s_out));

    // linear output base: p0 + n*(OC-1)*OPLANE, plus this half's oc offset
    int p0 = pr * 2;
    int n  = p0 / OPLANE;
    float* obase = out + p0 + (size_t)n * (OC - 1) * OPLANE
                       + (size_t)blockIdx.y * 64 * OPLANE;

#pragma unroll 4
    for (int oc = 0; oc < 64; oc++) {
        int4 wa = sw[oc * 2], wb = sw[oc * 2 + 1];
        int bi = wb.w;
        int a0 = dot7(x0a, x0b, wa, wb, bi);
        int a1 = dot7(x1a, x1b, wa, wb, bi);
        // magic rounding, both lanes at once: q = rint(a*kf) * s_out
        float f0 = (float)a0, f1 = (float)a1;
        unsigned long long p, q;
        asm("mov.b64 %0, {%1,%2};" : "=l"(p) : "f"(f0), "f"(f1));
        asm("fma.rn.f32x2 %0, %1, %2, %3;" : "=l"(q) : "l"(p), "l"(k2), "l"(m2));
        asm("add.rn.f32x2 %0, %1, %2;" : "=l"(q) : "l"(q), "l"(nm2));
        asm("mul.rn.f32x2 %0, %1, %2;" : "=l"(q) : "l"(q), "l"(s2));
        // streaming 8B store (write-once output, evict-first)
        asm volatile("st.global.cs.b64 [%0], %1;"
                     :: "l"(obase + (size_t)oc * OPLANE), "l"(q) : "memory");
    }
}

// ---------------- launcher --------------------------------------------------------
extern "C" void kernel_launch(void* const* d_in, const int* in_sizes, int n_in,
                              void* d_out, int out_size) {
    const float *x = nullptr, *w = nullptr, *b = nullptr;
    for (int i = 0; i < n_in; i++) {
        if (in_sizes[i] == N_IMG * C_IN * PLANE)      x = (const float*)d_in[i];
        else if (in_sizes[i] == OC * C_IN * 9)        w = (const float*)d_in[i];
        else if (in_sizes[i] == OC)                   b = (const float*)d_in[i];
    }
    float* out = (float*)d_out;

    void* scal_addr = nullptr;
    cudaGetSymbolAddress(&scal_addr, g_scal);
    cudaMemsetAsync(scal_addr, 0, 3 * sizeof(unsigned), 0);

    int n4 = (N_IMG * C_IN * PLANE) / 4;
    k_absmax<<<(n4 + 255) / 256, 256>>>(x, w);

    k_quant<<<QBLOCKS + 1, 256>>>(x, w, b);

    int cblocks = (NPAIRS + 255) / 256;   // 1541
    dim3 mg(cblocks, 2);
    k_convmax<<<mg, 256>>>();
    k_convstore<<<mg, 256>>>(out);
}

// round 16
// speedup vs baseline: 1.0845x; 1.0109x over previous
#include <cuda_runtime.h>
#include <cuda_bf16.h>
#include <cstdint>

// Problem shape (fixed)
#define N_IMG  16
#define C_IN   3
#define H_IN   224
#define W_IN   224
#define OC     128
#define OH     222
#define OW     222
#define PLANE  (H_IN * W_IN)            // 50176
#define NPIX   (N_IMG * PLANE)          // 802816
#define OPLANE (OH * OW)                // 49284 (even)
#define NPOS   (N_IMG * OPLANE)         // 788544
#define NPAIRS (NPOS / 2)               // 394272 conv threads (2 positions each)
#define STSPLIT 4                        // convstore oc split
#define STOCS   (OC / STSPLIT)           // 32 ocs per convstore thread

// ---------------- device scratch ------------------------------------------------
// g_scal[0] = amax_x bits, g_scal[1] = amax_w bits, g_scal[2] = amax_v (int)
__device__ unsigned g_scal[3];
__device__ int   g_xq[NPIX];        // packed char4 (c0,c1,c2,0) per pixel
__device__ int4  g_im[NPOS * 2];    // dense im2col: 27 bytes + 5 zero pad (32B/pos)
__device__ int4  g_wqp[OC * 2];     // per oc: 27 wt bytes + pad; word 7 = bias int

static __device__ __forceinline__ int pack4(int a, int b, int c, int d) {
    return (a & 0xFF) | ((b & 0xFF) << 8) | ((c & 0xFF) << 16) | ((d & 0xFF) << 24);
}

// ---------------- K1: abs-max of x (float4 grid) and W --------------------------
__global__ void k_absmax(const float* __restrict__ x, const float* __restrict__ w) {
    int i = blockIdx.x * blockDim.x + threadIdx.x;
    float m = 0.0f;
    if (i < (N_IMG * C_IN * PLANE) / 4) {
        float4 v = reinterpret_cast<const float4*>(x)[i];
        m = fmaxf(fmaxf(fabsf(v.x), fabsf(v.y)), fmaxf(fabsf(v.z), fabsf(v.w)));
    }
    unsigned um = __reduce_max_sync(0xFFFFFFFFu, __float_as_uint(m));
    if ((threadIdx.x & 31) == 0 && um) atomicMax(&g_scal[0], um);

    if (blockIdx.x == 0) {
        float wm = 0.0f;
        for (int j = threadIdx.x; j < OC * C_IN * 9; j += blockDim.x)
            wm = fmaxf(wm, fabsf(w[j]));
        unsigned uw = __reduce_max_sync(0xFFFFFFFFu, __float_as_uint(wm));
        if ((threadIdx.x & 31) == 0) atomicMax(&g_scal[1], uw);
    }
}

// ---------------- K2: quantize x (4 pixels/thread) ; W -> dense 32B records -----
// record byte order: i = tap*3 + channel (i in [0,27)); word 7 = bias int
#define QBLOCKS (NPIX / 1024)   // 784, exact
__global__ void k_quant(const float* __restrict__ x, const float* __restrict__ w,
                        const float* __restrict__ b) {
    const float s_in = fmaxf(__fdiv_rn(__uint_as_float(g_scal[0]), 127.0f), 1e-8f);
    if (blockIdx.x < QBLOCKS) {
        int idx = (blockIdx.x * 256 + threadIdx.x) * 4;
        int n  = idx / PLANE;
        int hw = idx - n * PLANE;
        const float* xp = x + (size_t)n * C_IN * PLANE + hw;
        float4 c0 = *reinterpret_cast<const float4*>(xp);
        float4 c1 = *reinterpret_cast<const float4*>(xp + PLANE);
        float4 c2 = *reinterpret_cast<const float4*>(xp + 2 * PLANE);
        const float ri = __fdiv_rn(1.0f, s_in);
        int4 o;
        {
            int q0 = (int)fminf(fmaxf(rintf(c0.x * ri), -128.f), 127.f);
            int q1 = (int)fminf(fmaxf(rintf(c1.x * ri), -128.f), 127.f);
            int q2 = (int)fminf(fmaxf(rintf(c2.x * ri), -128.f), 127.f);
            o.x = pack4(q0, q1, q2, 0);
        }
        {
            int q0 = (int)fminf(fmaxf(rintf(c0.y * ri), -128.f), 127.f);
            int q1 = (int)fminf(fmaxf(rintf(c1.y * ri), -128.f), 127.f);
            int q2 = (int)fminf(fmaxf(rintf(c2.y * ri), -128.f), 127.f);
            o.y = pack4(q0, q1, q2, 0);
        }
        {
            int q0 = (int)fminf(fmaxf(rintf(c0.z * ri), -128.f), 127.f);
            int q1 = (int)fminf(fmaxf(rintf(c1.z * ri), -128.f), 127.f);
            int q2 = (int)fminf(fmaxf(rintf(c2.z * ri), -128.f), 127.f);
            o.z = pack4(q0, q1, q2, 0);
        }
        {
            int q0 = (int)fminf(fmaxf(rintf(c0.w * ri), -128.f), 127.f);
            int q1 = (int)fminf(fmaxf(rintf(c1.w * ri), -128.f), 127.f);
            int q2 = (int)fminf(fmaxf(rintf(c2.w * ri), -128.f), 127.f);
            o.w = pack4(q0, q1, q2, 0);
        }
        *reinterpret_cast<int4*>(g_xq + idx) = o;
    } else if (threadIdx.x < OC) {
        const float s_w = fmaxf(__fdiv_rn(__uint_as_float(g_scal[1]), 7.0f), 1e-8f);
        int oc = threadIdx.x;
        int m[28];
#pragma unroll
        for (int i = 0; i < 27; i++) {
            int t = i / 3, c = i - t * 3;              // tap-major, channel-minor
            float v = rintf(__fdiv_rn(w[oc * 27 + c * 9 + t], s_w));
            v = fminf(fmaxf(v, -7.0f), 7.0f);
            m[i] = (int)v;
        }
        m[27] = 0;
        int wd[8];
#pragma unroll
        for (int j = 0; j < 7; j++)
            wd[j] = pack4(m[4 * j], m[4 * j + 1], m[4 * j + 2], m[4 * j + 3]);
        float s_b = s_in * s_w;
        float bt = rintf(__fdiv_rn(b[oc], s_b));
        bt = fminf(fmaxf(bt, -2.0e9f), 2.0e9f);
        wd[7] = (int)bt;                               // bias int (never multiplied)
        g_wqp[oc * 2]     = make_int4(wd[0], wd[1], wd[2], wd[3]);
        g_wqp[oc * 2 + 1] = make_int4(wd[4], wd[5], wd[6], wd[7]);
    }
}

// pack one 32B im2col record from 9 pixel words
static __device__ __forceinline__ void pack_rec(int t0, int t1, int t2,
                                                int t3, int t4, int t5,
                                                int t6, int t7, int t8,
                                                int4& lo, int4& hi) {
    lo.x = __byte_perm(t0, t1, 0x4210);
    lo.y = __byte_perm(t1, t2, 0x5421);
    lo.z = __byte_perm(t2, t3, 0x6542);
    lo.w = __byte_perm(t4, t5, 0x4210);
    hi.x = __byte_perm(t5, t6, 0x5421);
    hi.y = __byte_perm(t6, t7, 0x6542);
    hi.z = __byte_perm(t8, 0,  0x4210);
    hi.w = 0;
}

// 7-word dp4a dot as TWO independent chains (4 + 3), merged by one IADD
static __device__ __forceinline__ int dot7(const int4& xa, const int4& xb,
                                           const int4& wa, const int4& wb, int init) {
    int s = __dp4a(xa.x, wa.x, init);
    s = __dp4a(xa.y, wa.y, s);
    s = __dp4a(xa.z, wa.z, s);
    s = __dp4a(xa.w, wa.w, s);
    int t = __dp4a(xb.x, wb.x, 0);
    t = __dp4a(xb.y, wb.y, t);
    t = __dp4a(xb.z, wb.z, t);
    return s + t;
}

// ---------------- K3: FUSED im2col + max pass, oc split across gridDim.y --------
// gridDim = (1541, 2): y selects a 64-oc half. Only y==0 writes g_im.
__global__ void __launch_bounds__(256, 6) k_convmax() {
    __shared__ int4 sw[64 * 2];                        // 2KB: this half's weights
    if (threadIdx.x < 128)
        sw[threadIdx.x] = g_wqp[blockIdx.y * 128 + threadIdx.x];
    __syncthreads();

    int pr = blockIdx.x * 256 + threadIdx.x;           // pair index
    if (pr >= NPAIRS) return;
    int n  = pr / (OPLANE / 2);
    int r2 = (pr - n * (OPLANE / 2)) * 2;
    int oh = r2 / OW;
    int ow = r2 - oh * OW;                             // even, <= 220
    const int* xp = g_xq + (n * H_IN + oh) * W_IN + ow;
    int w00 = xp[0],        w01 = xp[1],            w02 = xp[2],            w03 = xp[3];
    int w10 = xp[W_IN],     w11 = xp[W_IN + 1],     w12 = xp[W_IN + 2],     w13 = xp[W_IN + 3];
    int w20 = xp[2 * W_IN], w21 = xp[2 * W_IN + 1], w22 = xp[2 * W_IN + 2], w23 = xp[2 * W_IN + 3];

    int4 x0a, x0b, x1a, x1b;
    pack_rec(w00, w01, w02, w10, w11, w12, w20, w21, w22, x0a, x0b);
    pack_rec(w01, w02, w03, w11, w12, w13, w21, w22, w23, x1a, x1b);
    if (blockIdx.y == 0) {
        int4* op = g_im + (size_t)pr * 4;
        op[0] = x0a; op[1] = x0b; op[2] = x1a; op[3] = x1b;
    }

    int mx = -2147483647, mn = 2147483647;
#pragma unroll 4
    for (int oc = 0; oc < 64; oc++) {
        int4 wa = sw[oc * 2], wb = sw[oc * 2 + 1];
        int bi = wb.w;
        int a0 = dot7(x0a, x0b, wa, wb, bi);
        int a1 = dot7(x1a, x1b, wa, wb, bi);
        mx = __vimax3_s32(mx, a0, a1);
        mn = __vimin3_s32(mn, a0, a1);
    }
    int am = __vimax3_s32(mx, -mn, 0);                 // |max| and clamp >= 0
    am = (int)__reduce_max_sync(0xFFFFFFFFu, (unsigned)am);
    if ((threadIdx.x & 31) == 0) atomicMax((int*)&g_scal[2], am);
}

// ---------------- K4: store pass, oc split across gridDim.y = 4 ------------------
// gridDim = (1541, 4): y selects a 32-oc slice. f32x2 epilogue + streaming stores.
__global__ void __launch_bounds__(256, 6) k_convstore(float* __restrict__ out) {
    __shared__ int4 sw[STOCS * 2];                     // 1KB: this slice's weights
    if (threadIdx.x < STOCS * 2)
        sw[threadIdx.x] = g_wqp[blockIdx.y * (STOCS * 2) + threadIdx.x];
    __syncthreads();

    int pr = blockIdx.x * 256 + threadIdx.x;
    if (pr >= NPAIRS) return;

    const int4* ip = g_im + (size_t)pr * 4;            // 64B consecutive per thread
    int4 x0a = ip[0], x0b = ip[1];
    int4 x1a = ip[2], x1b = ip[3];

    const float s_in = fmaxf(__fdiv_rn(__uint_as_float(g_scal[0]), 127.0f), 1e-8f);
    const float s_w  = fmaxf(__fdiv_rn(__uint_as_float(g_scal[1]), 7.0f), 1e-8f);
    float s_b   = s_in * s_w;
    float maxy  = s_b * (float)(int)g_scal[2];
    float s_out = fmaxf(__fdiv_rn(maxy, 127.0f), 1e-8f);
    float kf    = __fdiv_rn(s_b, s_out);
    const float MAGIC = 12582912.0f;                   // 1.5 * 2^23

    // packed f32x2 constants
    unsigned long long k2, m2, nm2, s2;
    asm("mov.b64 %0, {%1,%1};" : "=l"(k2)  : "f"(kf));
    asm("mov.b64 %0, {%1,%1};" : "=l"(m2)  : "f"(MAGIC));
    asm("mov.b64 %0, {%1,%1};" : "=l"(nm2) : "f"(-MAGIC));
    asm("mov.b64 %0, {%1,%1};" : "=l"(s2)  : "f"(s_out));

    // linear output base: p0 + n*(OC-1)*OPLANE, plus this slice's oc offset
    int p0 = pr * 2;
    int n  = p0 / OPLANE;
    float* obase = out + p0 + (size_t)n * (OC - 1) * OPLANE
                       + (size_t)blockIdx.y * STOCS * OPLANE;

#pragma unroll 4
    for (int oc = 0; oc < STOCS; oc++) {
        int4 wa = sw[oc * 2], wb = sw[oc * 2 + 1];
        int bi = wb.w;
        int a0 = dot7(x0a, x0b, wa, wb, bi);
        int a1 = dot7(x1a, x1b, wa, wb, bi);
        // magic rounding, both lanes at once: q = rint(a*kf) * s_out
        float f0 = (float)a0, f1 = (float)a1;
        unsigned long long p, q;
        asm("mov.b64 %0, {%1,%2};" : "=l"(p) : "f"(f0), "f"(f1));
        asm("fma.rn.f32x2 %0, %1, %2, %3;" : "=l"(q) : "l"(p), "l"(k2), "l"(m2));
        asm("add.rn.f32x2 %0, %1, %2;" : "=l"(q) : "l"(q), "l"(nm2));
        asm("mul.rn.f32x2 %0, %1, %2;" : "=l"(q) : "l"(q), "l"(s2));
        // streaming 8B store (write-once output, evict-first)
        asm volatile("st.global.cs.b64 [%0], %1;"
                     :: "l"(obase + (size_t)oc * OPLANE), "l"(q) : "memory");
    }
}

// ---------------- launcher --------------------------------------------------------
extern "C" void kernel_launch(void* const* d_in, const int* in_sizes, int n_in,
                              void* d_out, int out_size) {
    const float *x = nullptr, *w = nullptr, *b = nullptr;
    for (int i = 0; i < n_in; i++) {
        if (in_sizes[i] == N_IMG * C_IN * PLANE)      x = (const float*)d_in[i];
        else if (in_sizes[i] == OC * C_IN * 9)        w = (const float*)d_in[i];
        else if (in_sizes[i] == OC)                   b = (const float*)d_in[i];
    }
    float* out = (float*)d_out;

    void* scal_addr = nullptr;
    cudaGetSymbolAddress(&scal_addr, g_scal);
    cudaMemsetAsync(scal_addr, 0, 3 * sizeof(unsigned), 0);

    int n4 = (N_IMG * C_IN * PLANE) / 4;
    k_absmax<<<(n4 + 255) / 256, 256>>>(x, w);

    k_quant<<<QBLOCKS + 1, 256>>>(x, w, b);

    int cblocks = (NPAIRS + 255) / 256;   // 1541
    dim3 mg(cblocks, 2);
    k_convmax<<<mg, 256>>>();
    dim3 sg(cblocks, STSPLIT);
    k_convstore<<<sg, 256>>>(out);
}

// round 17
// speedup vs baseline: 1.1269x; 1.0391x over previous
#include <cuda_runtime.h>
#include <cuda_bf16.h>
#include <cstdint>

// Problem shape (fixed)
#define N_IMG  16
#define C_IN   3
#define H_IN   224
#define W_IN   224
#define OC     128
#define OH     222
#define OW     222
#define PLANE  (H_IN * W_IN)            // 50176
#define NPIX   (N_IMG * PLANE)          // 802816
#define OPLANE (OH * OW)                // 49284 (even)
#define NPOS   (N_IMG * OPLANE)         // 788544
#define NPAIRS (NPOS / 2)               // 394272 conv threads (2 positions each)
#define STSPLIT 4                        // convstore oc split
#define STOCS   (OC / STSPLIT)           // 32 ocs per convstore thread

// ---------------- device scratch ------------------------------------------------
// g_scal[0] = amax_x bits, g_scal[1] = amax_w bits, g_scal[2] = amax_v (int)
__device__ unsigned g_scal[3];
__device__ int   g_xq[NPIX];        // packed char4 (c0,c1,c2,0) per pixel (3.2MB)
__device__ int4  g_wqp[OC * 2];     // per oc: 27 wt bytes + pad; word 7 = bias int

static __device__ __forceinline__ int pack4(int a, int b, int c, int d) {
    return (a & 0xFF) | ((b & 0xFF) << 8) | ((c & 0xFF) << 16) | ((d & 0xFF) << 24);
}

// ---------------- K1: abs-max of x (float4 grid) and W --------------------------
__global__ void k_absmax(const float* __restrict__ x, const float* __restrict__ w) {
    int i = blockIdx.x * blockDim.x + threadIdx.x;
    float m = 0.0f;
    if (i < (N_IMG * C_IN * PLANE) / 4) {
        float4 v = reinterpret_cast<const float4*>(x)[i];
        m = fmaxf(fmaxf(fabsf(v.x), fabsf(v.y)), fmaxf(fabsf(v.z), fabsf(v.w)));
    }
    unsigned um = __reduce_max_sync(0xFFFFFFFFu, __float_as_uint(m));
    if ((threadIdx.x & 31) == 0 && um) atomicMax(&g_scal[0], um);

    if (blockIdx.x == 0) {
        float wm = 0.0f;
        for (int j = threadIdx.x; j < OC * C_IN * 9; j += blockDim.x)
            wm = fmaxf(wm, fabsf(w[j]));
        unsigned uw = __reduce_max_sync(0xFFFFFFFFu, __float_as_uint(wm));
        if ((threadIdx.x & 31) == 0) atomicMax(&g_scal[1], uw);
    }
}

// ---------------- K2: quantize x (4 pixels/thread) ; W -> dense 32B records -----
// record byte order: i = tap*3 + channel (i in [0,27)); word 7 = bias int
#define QBLOCKS (NPIX / 1024)   // 784, exact
__global__ void k_quant(const float* __restrict__ x, const float* __restrict__ w,
                        const float* __restrict__ b) {
    const float s_in = fmaxf(__fdiv_rn(__uint_as_float(g_scal[0]), 127.0f), 1e-8f);
    if (blockIdx.x < QBLOCKS) {
        int idx = (blockIdx.x * 256 + threadIdx.x) * 4;
        int n  = idx / PLANE;
        int hw = idx - n * PLANE;
        const float* xp = x + (size_t)n * C_IN * PLANE + hw;
        float4 c0 = *reinterpret_cast<const float4*>(xp);
        float4 c1 = *reinterpret_cast<const float4*>(xp + PLANE);
        float4 c2 = *reinterpret_cast<const float4*>(xp + 2 * PLANE);
        const float ri = __fdiv_rn(1.0f, s_in);
        int4 o;
        {
            int q0 = (int)fminf(fmaxf(rintf(c0.x * ri), -128.f), 127.f);
            int q1 = (int)fminf(fmaxf(rintf(c1.x * ri), -128.f), 127.f);
            int q2 = (int)fminf(fmaxf(rintf(c2.x * ri), -128.f), 127.f);
            o.x = pack4(q0, q1, q2, 0);
        }
        {
            int q0 = (int)fminf(fmaxf(rintf(c0.y * ri), -128.f), 127.f);
            int q1 = (int)fminf(fmaxf(rintf(c1.y * ri), -128.f), 127.f);
            int q2 = (int)fminf(fmaxf(rintf(c2.y * ri), -128.f), 127.f);
            o.y = pack4(q0, q1, q2, 0);
        }
        {
            int q0 = (int)fminf(fmaxf(rintf(c0.z * ri), -128.f), 127.f);
            int q1 = (int)fminf(fmaxf(rintf(c1.z * ri), -128.f), 127.f);
            int q2 = (int)fminf(fmaxf(rintf(c2.z * ri), -128.f), 127.f);
            o.z = pack4(q0, q1, q2, 0);
        }
        {
            int q0 = (int)fminf(fmaxf(rintf(c0.w * ri), -128.f), 127.f);
            int q1 = (int)fminf(fmaxf(rintf(c1.w * ri), -128.f), 127.f);
            int q2 = (int)fminf(fmaxf(rintf(c2.w * ri), -128.f), 127.f);
            o.w = pack4(q0, q1, q2, 0);
        }
        *reinterpret_cast<int4*>(g_xq + idx) = o;
    } else if (threadIdx.x < OC) {
        const float s_w = fmaxf(__fdiv_rn(__uint_as_float(g_scal[1]), 7.0f), 1e-8f);
        int oc = threadIdx.x;
        int m[28];
#pragma unroll
        for (int i = 0; i < 27; i++) {
            int t = i / 3, c = i - t * 3;              // tap-major, channel-minor
            float v = rintf(__fdiv_rn(w[oc * 27 + c * 9 + t], s_w));
            v = fminf(fmaxf(v, -7.0f), 7.0f);
            m[i] = (int)v;
        }
        m[27] = 0;
        int wd[8];
#pragma unroll
        for (int j = 0; j < 7; j++)
            wd[j] = pack4(m[4 * j], m[4 * j + 1], m[4 * j + 2], m[4 * j + 3]);
        float s_b = s_in * s_w;
        float bt = rintf(__fdiv_rn(b[oc], s_b));
        bt = fminf(fmaxf(bt, -2.0e9f), 2.0e9f);
        wd[7] = (int)bt;                               // bias int (never multiplied)
        g_wqp[oc * 2]     = make_int4(wd[0], wd[1], wd[2], wd[3]);
        g_wqp[oc * 2 + 1] = make_int4(wd[4], wd[5], wd[6], wd[7]);
    }
}

// pack one 32B im2col record from 9 pixel words
static __device__ __forceinline__ void pack_rec(int t0, int t1, int t2,
                                                int t3, int t4, int t5,
                                                int t6, int t7, int t8,
                                                int4& lo, int4& hi) {
    lo.x = __byte_perm(t0, t1, 0x4210);
    lo.y = __byte_perm(t1, t2, 0x5421);
    lo.z = __byte_perm(t2, t3, 0x6542);
    lo.w = __byte_perm(t4, t5, 0x4210);
    hi.x = __byte_perm(t5, t6, 0x5421);
    hi.y = __byte_perm(t6, t7, 0x6542);
    hi.z = __byte_perm(t8, 0,  0x4210);
    hi.w = 0;
}

// load 12 pixel words and pack the pair's two records (registers only)
static __device__ __forceinline__ void load_pair_recs(int pr, int4& x0a, int4& x0b,
                                                      int4& x1a, int4& x1b) {
    int n  = pr / (OPLANE / 2);
    int r2 = (pr - n * (OPLANE / 2)) * 2;
    int oh = r2 / OW;
    int ow = r2 - oh * OW;                             // even, <= 220
    const int* xp = g_xq + (n * H_IN + oh) * W_IN + ow;
    int w00 = xp[0],        w01 = xp[1],            w02 = xp[2],            w03 = xp[3];
    int w10 = xp[W_IN],     w11 = xp[W_IN + 1],     w12 = xp[W_IN + 2],     w13 = xp[W_IN + 3];
    int w20 = xp[2 * W_IN], w21 = xp[2 * W_IN + 1], w22 = xp[2 * W_IN + 2], w23 = xp[2 * W_IN + 3];
    pack_rec(w00, w01, w02, w10, w11, w12, w20, w21, w22, x0a, x0b);
    pack_rec(w01, w02, w03, w11, w12, w13, w21, w22, w23, x1a, x1b);
}

// 7-word dp4a dot as TWO independent chains (4 + 3), merged by one IADD
static __device__ __forceinline__ int dot7(const int4& xa, const int4& xb,
                                           const int4& wa, const int4& wb, int init) {
    int s = __dp4a(xa.x, wa.x, init);
    s = __dp4a(xa.y, wa.y, s);
    s = __dp4a(xa.z, wa.z, s);
    s = __dp4a(xa.w, wa.w, s);
    int t = __dp4a(xb.x, wb.x, 0);
    t = __dp4a(xb.y, wb.y, t);
    t = __dp4a(xb.z, wb.z, t);
    return s + t;
}

// ---------------- K3: max pass, register im2col, oc split y=2 -------------------
__global__ void __launch_bounds__(256, 6) k_convmax() {
    __shared__ int4 sw[64 * 2];                        // 2KB: this half's weights
    if (threadIdx.x < 128)
        sw[threadIdx.x] = g_wqp[blockIdx.y * 128 + threadIdx.x];
    __syncthreads();

    int pr = blockIdx.x * 256 + threadIdx.x;           // pair index
    if (pr >= NPAIRS) return;

    int4 x0a, x0b, x1a, x1b;
    load_pair_recs(pr, x0a, x0b, x1a, x1b);

    int mx = -2147483647, mn = 2147483647;
#pragma unroll 4
    for (int oc = 0; oc < 64; oc++) {
        int4 wa = sw[oc * 2], wb = sw[oc * 2 + 1];
        int bi = wb.w;
        int a0 = dot7(x0a, x0b, wa, wb, bi);
        int a1 = dot7(x1a, x1b, wa, wb, bi);
        mx = __vimax3_s32(mx, a0, a1);
        mn = __vimin3_s32(mn, a0, a1);
    }
    int am = __vimax3_s32(mx, -mn, 0);                 // |max| and clamp >= 0
    am = (int)__reduce_max_sync(0xFFFFFFFFu, (unsigned)am);
    if ((threadIdx.x & 31) == 0) atomicMax((int*)&g_scal[2], am);
}

// ---------------- K4: store pass, register im2col, oc split y=4 ------------------
__global__ void __launch_bounds__(256, 6) k_convstore(float* __restrict__ out) {
    __shared__ int4 sw[STOCS * 2];                     // 1KB: this slice's weights
    if (threadIdx.x < STOCS * 2)
        sw[threadIdx.x] = g_wqp[blockIdx.y * (STOCS * 2) + threadIdx.x];
    __syncthreads();

    int pr = blockIdx.x * 256 + threadIdx.x;
    if (pr >= NPAIRS) return;

    int4 x0a, x0b, x1a, x1b;
    load_pair_recs(pr, x0a, x0b, x1a, x1b);

    const float s_in = fmaxf(__fdiv_rn(__uint_as_float(g_scal[0]), 127.0f), 1e-8f);
    const float s_w  = fmaxf(__fdiv_rn(__uint_as_float(g_scal[1]), 7.0f), 1e-8f);
    float s_b   = s_in * s_w;
    float maxy  = s_b * (float)(int)g_scal[2];
    float s_out = fmaxf(__fdiv_rn(maxy, 127.0f), 1e-8f);
    float kf    = __fdiv_rn(s_b, s_out);
    const float MAGIC = 12582912.0f;                   // 1.5 * 2^23

    // packed f32x2 constants
    unsigned long long k2, m2, nm2, s2;
    asm("mov.b64 %0, {%1,%1};" : "=l"(k2)  : "f"(kf));
    asm("mov.b64 %0, {%1,%1};" : "=l"(m2)  : "f"(MAGIC));
    asm("mov.b64 %0, {%1,%1};" : "=l"(nm2) : "f"(-MAGIC));
    asm("mov.b64 %0, {%1,%1};" : "=l"(s2)  : "f"(s_out));

    // linear output base: p0 + n*(OC-1)*OPLANE, plus this slice's oc offset
    int p0 = pr * 2;
    int n  = p0 / OPLANE;
    float* obase = out + p0 + (size_t)n * (OC - 1) * OPLANE
                       + (size_t)blockIdx.y * STOCS * OPLANE;

#pragma unroll 4
    for (int oc = 0; oc < STOCS; oc++) {
        int4 wa = sw[oc * 2], wb = sw[oc * 2 + 1];
        int bi = wb.w;
        int a0 = dot7(x0a, x0b, wa, wb, bi);
        int a1 = dot7(x1a, x1b, wa, wb, bi);
        // magic rounding, both lanes at once: q = rint(a*kf) * s_out
        float f0 = (float)a0, f1 = (float)a1;
        unsigned long long p, q;
        asm("mov.b64 %0, {%1,%2};" : "=l"(p) : "f"(f0), "f"(f1));
        asm("fma.rn.f32x2 %0, %1, %2, %3;" : "=l"(q) : "l"(p), "l"(k2), "l"(m2));
        asm("add.rn.f32x2 %0, %1, %2;" : "=l"(q) : "l"(q), "l"(nm2));
        asm("mul.rn.f32x2 %0, %1, %2;" : "=l"(q) : "l"(q), "l"(s2));
        // streaming 8B store (write-once output, evict-first)
        asm volatile("st.global.cs.b64 [%0], %1;"
                     :: "l"(obase + (size_t)oc * OPLANE), "l"(q) : "memory");
    }
}

// ---------------- launcher --------------------------------------------------------
extern "C" void kernel_launch(void* const* d_in, const int* in_sizes, int n_in,
                              void* d_out, int out_size) {
    const float *x = nullptr, *w = nullptr, *b = nullptr;
    for (int i = 0; i < n_in; i++) {
        if (in_sizes[i] == N_IMG * C_IN * PLANE)      x = (const float*)d_in[i];
        else if (in_sizes[i] == OC * C_IN * 9)        w = (const float*)d_in[i];
        else if (in_sizes[i] == OC)                   b = (const float*)d_in[i];
    }
    float* out = (float*)d_out;

    void* scal_addr = nullptr;
    cudaGetSymbolAddress(&scal_addr, g_scal);
    cudaMemsetAsync(scal_addr, 0, 3 * sizeof(unsigned), 0);

    int n4 = (N_IMG * C_IN * PLANE) / 4;
    k_absmax<<<(n4 + 255) / 256, 256>>>(x, w);

    k_quant<<<QBLOCKS + 1, 256>>>(x, w, b);

    int cblocks = (NPAIRS + 255) / 256;   // 1541
    dim3 mg(cblocks, 2);
    k_convmax<<<mg, 256>>>();
    dim3 sg(cblocks, STSPLIT);
    k_convstore<<<sg, 256>>>(out);
}